// round 8
// baseline (speedup 1.0000x reference)
#include <cuda_runtime.h>
#include <cstdint>

// ---------------------------------------------------------------------------
// PointCloudGenerator: neural-SDF sphere tracing, fully fused.
// R6: R2 shape (256 thr, grid 256, 2 CTAs/SM, k-chunk 64) with warp-layout
// remap (8tx x 4ty per warp: A 2wf + B 4wf per k-step, was 10) and float4
// packed layer-1 tables. Numerics identical to R2 (rel_err 8.751e-08).
// ---------------------------------------------------------------------------

// smem: Wb 16384 f (2 x 64x128 W2 stages; 'red' aliases), H1Tc 8192 f,
//       w1p 1024 f + b2s/w3s 512 f, ray state 1024 f => 27136 f = 108544 B
#define SMEM_FLOATS (16384 + 8192 + 1536 + 1024)
#define SMEM_BYTES  (SMEM_FLOATS * 4)

__device__ float g_c1[256];

__device__ __forceinline__ uint64_t pk2(float lo, float hi) {
    uint64_t r;
    asm("mov.b64 %0, {%1,%2};" : "=l"(r) : "f"(lo), "f"(hi));
    return r;
}
__device__ __forceinline__ void upk2(uint64_t v, float& lo, float& hi) {
    asm("mov.b64 {%0,%1}, %2;" : "=f"(lo), "=f"(hi) : "l"(v));
}
__device__ __forceinline__ void ffma2(uint64_t& d, uint64_t a, uint64_t b) {
    asm("fma.rn.f32x2 %0, %1, %2, %0;" : "+l"(d) : "l"(a), "l"(b));
}
__device__ __forceinline__ void cpa16(float* dst, const float* src) {
    uint32_t s = (uint32_t)__cvta_generic_to_shared(dst);
    asm volatile("cp.async.cg.shared.global [%0], [%1], 16;" :: "r"(s), "l"(src));
}

// c1[j] = b1[j] + sum_k lat[k] * W1[3+k][j]  -- one block per j, double accum
__global__ void c1_kernel(const float* __restrict__ lg, const float* __restrict__ le,
                          const float* __restrict__ la, const float* __restrict__ W1,
                          const float* __restrict__ b1) {
    int j = blockIdx.x;
    int t = threadIdx.x;
    double acc = 0.0;
    for (int k = t; k < 484; k += 128) {
        float lv = (k < 256) ? lg[k] : (k < 356 ? le[k - 256] : la[k - 356]);
        acc += (double)lv * (double)W1[(size_t)(3 + k) * 256 + j];
    }
    #pragma unroll
    for (int o = 16; o > 0; o >>= 1)
        acc += __shfl_down_sync(0xffffffffu, acc, o);
    __shared__ double part[4];
    if ((t & 31) == 0) part[t >> 5] = acc;
    __syncthreads();
    if (t == 0)
        g_c1[j] = (float)(part[0] + part[1] + part[2] + part[3] + (double)b1[j]);
}

__global__ void __launch_bounds__(256, 2)
trace_kernel(const float* __restrict__ W1, const float* __restrict__ W2,
             const float* __restrict__ b2g, const float* __restrict__ W3,
             const float* __restrict__ b3, float* __restrict__ out) {
    extern __shared__ float smf[];
    float*  Wb   = smf;                // 2 x [64 k][128 n] = 16384 f
    float*  red  = smf;                // [16][132] aliases Wb (post-GEMM only)
    float*  H1Tc = smf + 16384;        // [64 k][128 rays]  = 8192 f
    float4* w1p  = (float4*)(smf + 24576);   // [256] {w10,w11,w12,c1}
    float*  b2s  = smf + 25600;
    float*  w3s  = b2s + 256;
    float*  px   = smf + 26112;
    float*  py   = px + 128;
    float*  pz   = py + 128;
    float*  tt   = pz + 128;
    float*  ddx  = tt + 128;
    float*  ddy  = ddx + 128;
    float*  ddz  = ddy + 128;
    int*    act  = (int*)(ddz + 128);

    const int t  = threadIdx.x;               // 256 threads
    const int tx = (t & 7) + ((t >> 7) << 3); // 0..15 col group (8 cols each)
    const int ty = (t >> 3) & 15;             // 0..15 ray group (8 rays each)

    // static tables
    w1p[t] = make_float4(W1[t], W1[256 + t], W1[512 + t], g_c1[t]);
    b2s[t] = b2g[t];
    w3s[t] = W3[t * 4];   // only column 0 of W3 is live

    // ray setup (mirrors _rays in fp32)
    if (t < 128) {
        int g    = blockIdx.x * 128 + t;
        int view = g >> 14;
        int pix  = g & 16383;
        int iu = pix >> 7, jv = pix & 127;
        float u = (iu + 0.5f) / 128.0f - 0.5f;
        float v = 0.5f - (jv + 0.5f) / 128.0f;
        float nrm = sqrtf(__fadd_rn(__fadd_rn(__fmul_rn(u, u), __fmul_rn(v, v)), 1.0f));
        float d0x = u / nrm, d0y = v / nrm, d0z = -1.0f / nrm;
        float c = 0.86602540378443865f;          // cos(30 deg)
        float s = view ? 0.5f : -0.5f;           // sin(rho), rho = -30, +30
        float dirx = __fadd_rn(__fmul_rn(c, d0x), __fmul_rn(s, d0z));
        float diry = d0y;
        float dirz = __fadd_rn(__fmul_rn(-s, d0x), __fmul_rn(c, d0z));
        ddx[t] = dirx; ddy[t] = diry; ddz[t] = dirz;
        px[t] = __fadd_rn(__fmul_rn(s, 2.2f), __fmul_rn(2.2f, dirx));
        py[t] = __fmul_rn(2.2f, diry);
        pz[t] = __fadd_rn(__fmul_rn(c, 2.2f), __fmul_rn(2.2f, dirz));
        tt[t] = 0.0f;
        act[t] = 1;
    }
    __syncthreads();

    float dcur = 0.0f;

    for (int e = 0; e < 7; ++e) {
        float sp[8];
        #pragma unroll
        for (int q = 0; q < 8; ++q) sp[q] = 0.0f;

        #pragma unroll 1
        for (int nh = 0; nh < 2; ++nh) {
            uint64_t acc[4][8];     // 4 ray-pairs x 8 cols
            #pragma unroll
            for (int p = 0; p < 4; ++p)
                #pragma unroll
                for (int n = 0; n < 8; ++n) acc[p][n] = 0ull;

            const float* wsrc = W2 + nh * 128;
            const int r0 = t >> 5;          // 0..7
            const int c0 = (t & 31) * 4;    // 0..124

            auto issue = [&](int kc, int b) {
                float*       dst = Wb + b * 8192 + r0 * 128 + c0;
                const float* src = wsrc + (size_t)(kc * 64 + r0) * 256 + c0;
                #pragma unroll
                for (int i = 0; i < 8; ++i)
                    cpa16(dst + i * 1024, src + i * 2048);
                asm volatile("cp.async.commit_group;" ::: "memory");
            };
            issue(0, 0);
            issue(1, 1);

            #pragma unroll 1
            for (int kc = 0; kc < 4; ++kc) {
                // ---- layer-1 chunk: H1Tc[kl][r], j = kc*64 + kl ----
                {
                    int r = t & 127, half = t >> 7;
                    float x = px[r], yv = py[r], zv = pz[r];
                    const int jb = kc * 64 + half * 32;
                    #pragma unroll 8
                    for (int jj = 0; jj < 32; ++jj) {
                        int j = jb + jj;
                        float4 w = w1p[j];
                        float h = fmaf(x, w.x, fmaf(yv, w.y, fmaf(zv, w.z, w.w)));
                        H1Tc[(half * 32 + jj) * 128 + r] = fmaxf(h, 0.0f);
                    }
                }
                if (kc == 3) asm volatile("cp.async.wait_group 0;" ::: "memory");
                else         asm volatile("cp.async.wait_group 1;" ::: "memory");
                __syncthreads();

                const float* Bp = Wb + (kc & 1) * 8192 + tx * 8;
                const float* Ap = H1Tc + ty * 8;
                #pragma unroll 4
                for (int kk = 0; kk < 64; ++kk) {
                    ulonglong2 A0 = *(const ulonglong2*)(Ap + kk * 128);
                    ulonglong2 A1 = *(const ulonglong2*)(Ap + kk * 128 + 4);
                    uint64_t ap[4] = { A0.x, A0.y, A1.x, A1.y };
                    float4 b0 = *(const float4*)(Bp + kk * 128);
                    float4 b1 = *(const float4*)(Bp + kk * 128 + 4);
                    uint64_t bd[8] = { pk2(b0.x, b0.x), pk2(b0.y, b0.y),
                                       pk2(b0.z, b0.z), pk2(b0.w, b0.w),
                                       pk2(b1.x, b1.x), pk2(b1.y, b1.y),
                                       pk2(b1.z, b1.z), pk2(b1.w, b1.w) };
                    #pragma unroll
                    for (int p = 0; p < 4; ++p)
                        #pragma unroll
                        for (int n = 0; n < 8; ++n)
                            ffma2(acc[p][n], ap[p], bd[n]);
                }
                __syncthreads();
                if (kc < 2) issue(kc + 2, kc & 1);
            }

            // epilogue: bias + relu + partial dot with W3[:,0]
            #pragma unroll
            for (int p = 0; p < 4; ++p) {
                #pragma unroll
                for (int n = 0; n < 8; ++n) {
                    float lo, hi;
                    upk2(acc[p][n], lo, hi);
                    int col = nh * 128 + tx * 8 + n;
                    lo = fmaxf(__fadd_rn(lo, b2s[col]), 0.0f);
                    hi = fmaxf(__fadd_rn(hi, b2s[col]), 0.0f);
                    float w3v = w3s[col];
                    sp[2 * p]     = fmaf(lo, w3v, sp[2 * p]);
                    sp[2 * p + 1] = fmaf(hi, w3v, sp[2 * p + 1]);
                }
            }
        }

        // red aliases Wb: all GEMM reads of Wb completed (sync after kc=3)
        #pragma unroll
        for (int q = 0; q < 8; ++q) red[tx * 132 + ty * 8 + q] = sp[q];
        __syncthreads();

        // ---- sdf + ray update (one thread per ray) ----
        int pred = 0;
        if (t < 128) {
            float ssum = 0.0f;
            #pragma unroll
            for (int k2 = 0; k2 < 16; ++k2) ssum = __fadd_rn(ssum, red[k2 * 132 + t]);
            float res = __fadd_rn(ssum, b3[0]);
            float x = px[t], yv = py[t], zv = pz[t];
            float nrm = sqrtf(__fadd_rn(__fadd_rn(__fmul_rn(x, x), __fmul_rn(yv, yv)),
                                        __fmul_rn(zv, zv)));
            float d = __fadd_rn(__fsub_rn(nrm, 0.7f), res);
            dcur = d;
            if (e < 6) {
                int a   = act[t];
                int hit = fabsf(d) < 1e-3f;
                float adv = (a && !hit) ? __fmul_rn(1.41421356237309515f, d) : 0.0f;
                px[t] = __fadd_rn(x,  __fmul_rn(adv, ddx[t]));
                py[t] = __fadd_rn(yv, __fmul_rn(adv, ddy[t]));
                pz[t] = __fadd_rn(zv, __fmul_rn(adv, ddz[t]));
                float tn = __fadd_rn(tt[t], adv);
                tt[t] = tn;
                act[t] = (a && !hit && (tn < 3.5f)) ? 1 : 0;
                pred = (adv != 0.0f);
            }
        }
        int anyAdv = __syncthreads_or(pred);
        // if no ray moved, every remaining eval is bit-identical to dcur
        if (e < 6 && !anyAdv) break;
    }

    if (t < 128) {
        int g = blockIdx.x * 128 + t;
        bool m = fabsf(dcur) < 1e-3f;
        out[3 * g + 0] = m ? px[t] : 0.0f;
        out[3 * g + 1] = m ? py[t] : 0.0f;
        out[3 * g + 2] = m ? pz[t] : 0.0f;
    }
}

extern "C" void kernel_launch(void* const* d_in, const int* in_sizes, int n_in,
                              void* d_out, int out_size) {
    const float* lg = (const float*)d_in[0];
    const float* le = (const float*)d_in[1];
    const float* la = (const float*)d_in[2];
    const float* W1 = (const float*)d_in[3];
    const float* b1 = (const float*)d_in[4];
    const float* W2 = (const float*)d_in[5];
    const float* b2 = (const float*)d_in[6];
    const float* W3 = (const float*)d_in[7];
    const float* b3 = (const float*)d_in[8];
    float* out = (float*)d_out;

    cudaFuncSetAttribute(trace_kernel, cudaFuncAttributeMaxDynamicSharedMemorySize,
                         SMEM_BYTES);
    c1_kernel<<<256, 128>>>(lg, le, la, W1, b1);
    trace_kernel<<<256, 256, SMEM_BYTES>>>(W1, W2, b2, W3, b3, out);
}

// round 10
// speedup vs baseline: 1.1422x; 1.1422x over previous
#include <cuda_runtime.h>
#include <cstdint>

// ---------------------------------------------------------------------------
// PointCloudGenerator: neural-SDF sphere tracing, tensor-core layer-2 GEMM.
// R10: mma.sync m16n8k8 TF32 (sm_80+ PTX, works on harness's sm_100 target)
// with full 4-term hi/lo split (fp32-class accuracy). A fragments computed
// in-register from layer-1 (never staged); B pre-split + pre-arranged in
// fragment order, streamed via double-buffered cp.async. 256 CTAs, 1 wave.
// ---------------------------------------------------------------------------

#define OFF_STAGE 0
#define STAGE_F   8192          // floats per stage (hi 4096 + lo 4096)
#define OFF_W1P   16384
#define OFF_B2S   17408
#define OFF_W3S   17664
#define OFF_PX    17920
#define OFF_PY    18048
#define OFF_PZ    18176
#define OFF_TT    18304
#define OFF_DDX   18432
#define OFF_DDY   18560
#define OFF_DDZ   18688
#define OFF_ACT   18816
#define OFF_RED   18944
#define SMEM_FLOATS 19072
#define SMEM_BYTES  (SMEM_FLOATS * 4)

__device__ float g_c1[256];
__device__ float g_Bfh[65536];   // W2^T hi, fragment-order layout
__device__ float g_Bfl[65536];   // W2^T lo, fragment-order layout

__device__ __forceinline__ float t13(float a) {      // truncate to tf32 bits
    return __uint_as_float(__float_as_uint(a) & 0xFFFFE000u);
}
__device__ __forceinline__ void cpa16(float* dst, const float* src) {
    uint32_t s;
    asm("{ .reg .u64 t; cvta.to.shared.u64 t, %1; cvt.u32.u64 %0, t; }"
        : "=r"(s) : "l"(dst));
    asm volatile("cp.async.cg.shared.global [%0], [%1], 16;" :: "r"(s), "l"(src));
}
__device__ __forceinline__ void mmaop(float* c, const uint32_t* a,
                                      uint32_t b0, uint32_t b1) {
    asm("mma.sync.aligned.m16n8k8.row.col.f32.tf32.tf32.f32 "
        "{%0,%1,%2,%3},{%4,%5,%6,%7},{%8,%9},{%0,%1,%2,%3};"
        : "+f"(c[0]), "+f"(c[1]), "+f"(c[2]), "+f"(c[3])
        : "r"(a[0]), "r"(a[1]), "r"(a[2]), "r"(a[3]), "r"(b0), "r"(b1));
}

// c1[j] = b1[j] + sum_k lat[k] * W1[3+k][j]  -- one block per j, double accum
__global__ void c1_kernel(const float* __restrict__ lg, const float* __restrict__ le,
                          const float* __restrict__ la, const float* __restrict__ W1,
                          const float* __restrict__ b1) {
    int j = blockIdx.x;
    int t = threadIdx.x;
    double acc = 0.0;
    for (int k = t; k < 484; k += 128) {
        float lv = (k < 256) ? lg[k] : (k < 356 ? le[k - 256] : la[k - 356]);
        acc += (double)lv * (double)W1[(size_t)(3 + k) * 256 + j];
    }
    #pragma unroll
    for (int o = 16; o > 0; o >>= 1)
        acc += __shfl_down_sync(0xffffffffu, acc, o);
    __shared__ double part[4];
    if ((t & 31) == 0) part[t >> 5] = acc;
    __syncthreads();
    if (t == 0)
        g_c1[j] = (float)(part[0] + part[1] + part[2] + part[3] + (double)b1[j]);
}

// split W2 (k-major [k][n]) into hi/lo, stored in m16n8k8 B-fragment order:
// addr = ((n>>3)*32 + (k>>3))*64 + ((n&7)*4 + (k&3))*2 + ((k>>2)&1)
__global__ void bsplit_kernel(const float* __restrict__ W2) {
    int n = blockIdx.x, k = threadIdx.x;
    float w = W2[k * 256 + n];
    float hi = t13(w);
    float lo = t13(__fsub_rn(w, hi));
    int addr = ((n >> 3) * 32 + (k >> 3)) * 64 + ((n & 7) * 4 + (k & 3)) * 2 +
               ((k >> 2) & 1);
    g_Bfh[addr] = hi;
    g_Bfl[addr] = lo;
}

__global__ void __launch_bounds__(256, 2)
trace_kernel(const float* __restrict__ W1, const float* __restrict__ b2g,
             const float* __restrict__ W3, const float* __restrict__ b3,
             float* __restrict__ out) {
    extern __shared__ float smf[];
    float4* w1p = (float4*)(smf + OFF_W1P);   // [256] {w10,w11,w12,c1}
    float*  b2s = smf + OFF_B2S;
    float*  w3s = smf + OFF_W3S;
    float*  px  = smf + OFF_PX;
    float*  py  = smf + OFF_PY;
    float*  pz  = smf + OFF_PZ;
    float*  tt  = smf + OFF_TT;
    float*  ddx = smf + OFF_DDX;
    float*  ddy = smf + OFF_DDY;
    float*  ddz = smf + OFF_DDZ;
    int*    act = (int*)(smf + OFF_ACT);
    float*  red = smf + OFF_RED;

    const int t    = threadIdx.x;
    const int lane = t & 31;
    const int wid  = t >> 5;
    const int rlo  = wid * 16 + (lane >> 2);   // this thread's low ray row

    // tables
    w1p[t] = make_float4(W1[t], W1[256 + t], W1[512 + t], g_c1[t]);
    b2s[t] = b2g[t];
    w3s[t] = W3[t * 4];     // only column 0 of W3 is live

    // ray setup (mirrors _rays in fp32)
    if (t < 128) {
        int g    = blockIdx.x * 128 + t;
        int view = g >> 14;
        int pix  = g & 16383;
        int iu = pix >> 7, jv = pix & 127;
        float u = (iu + 0.5f) / 128.0f - 0.5f;
        float v = 0.5f - (jv + 0.5f) / 128.0f;
        float nrm = sqrtf(__fadd_rn(__fadd_rn(__fmul_rn(u, u), __fmul_rn(v, v)), 1.0f));
        float d0x = u / nrm, d0y = v / nrm, d0z = -1.0f / nrm;
        float c = 0.86602540378443865f;          // cos(30 deg)
        float s = view ? 0.5f : -0.5f;           // sin(rho), rho = -30, +30
        float dirx = __fadd_rn(__fmul_rn(c, d0x), __fmul_rn(s, d0z));
        float diry = d0y;
        float dirz = __fadd_rn(__fmul_rn(-s, d0x), __fmul_rn(c, d0z));
        ddx[t] = dirx; ddy[t] = diry; ddz[t] = dirz;
        px[t] = __fadd_rn(__fmul_rn(s, 2.2f), __fmul_rn(2.2f, dirx));
        py[t] = __fmul_rn(2.2f, diry);
        pz[t] = __fadd_rn(__fmul_rn(c, 2.2f), __fmul_rn(2.2f, dirz));
        tt[t] = 0.0f;
        act[t] = 1;
    }
    __syncthreads();

    const float b3v = b3[0];
    float dcur = 0.0f;

    // stream B chunk (nc, kc) into stage s: 64 frag-blocks x 64 floats, hi+lo
    auto issue = [&](int nc, int kc, int s) {
        float* stH = smf + OFF_STAGE + s * STAGE_F;
        float* stL = stH + 4096;
        #pragma unroll
        for (int i = 0; i < 4; ++i) {
            int tr = t + i * 256;               // 0..1023
            int bl = tr >> 4, q = tr & 15;
            int gb = nc * 512 + kc * 4 + (bl >> 2) * 32 + (bl & 3);
            cpa16(stH + bl * 64 + q * 4, g_Bfh + gb * 64 + q * 4);
            cpa16(stL + bl * 64 + q * 4, g_Bfl + gb * 64 + q * 4);
        }
        asm volatile("cp.async.commit_group;" ::: "memory");
    };

    for (int e = 0; e < 7; ++e) {
        // this thread's two rays, in registers
        float xlo = px[rlo],     ylo = py[rlo],     zlo = pz[rlo];
        float xhi = px[rlo + 8], yhi = py[rlo + 8], zhi = pz[rlo + 8];
        float sp0 = 0.0f, sp1 = 0.0f;

        #pragma unroll 1
        for (int nc = 0; nc < 2; ++nc) {
            float acc[16][4];
            #pragma unroll
            for (int i = 0; i < 16; ++i)
                #pragma unroll
                for (int j = 0; j < 4; ++j) acc[i][j] = 0.0f;

            issue(nc, 0, 0);
            issue(nc, 1, 1);

            #pragma unroll 1
            for (int kc = 0; kc < 8; ++kc) {
                if (kc < 7) asm volatile("cp.async.wait_group 1;" ::: "memory");
                else        asm volatile("cp.async.wait_group 0;" ::: "memory");
                __syncthreads();

                const float* stH = smf + OFF_STAGE + (kc & 1) * STAGE_F;
                #pragma unroll
                for (int k8 = 0; k8 < 4; ++k8) {
                    // A fragment: layer-1 for (2 rays) x (2 k), in-register
                    int k0 = kc * 32 + k8 * 8 + (lane & 3);
                    float4 w0 = w1p[k0];
                    float4 w1 = w1p[k0 + 4];
                    float h00 = fmaxf(fmaf(xlo, w0.x, fmaf(ylo, w0.y,
                                      fmaf(zlo, w0.z, w0.w))), 0.0f);
                    float h10 = fmaxf(fmaf(xhi, w0.x, fmaf(yhi, w0.y,
                                      fmaf(zhi, w0.z, w0.w))), 0.0f);
                    float h01 = fmaxf(fmaf(xlo, w1.x, fmaf(ylo, w1.y,
                                      fmaf(zlo, w1.z, w1.w))), 0.0f);
                    float h11 = fmaxf(fmaf(xhi, w1.x, fmaf(yhi, w1.y,
                                      fmaf(zhi, w1.z, w1.w))), 0.0f);
                    float f0 = t13(h00), f1 = t13(h10), f2 = t13(h01), f3 = t13(h11);
                    uint32_t ah[4] = { __float_as_uint(f0), __float_as_uint(f1),
                                       __float_as_uint(f2), __float_as_uint(f3) };
                    uint32_t al[4] = {
                        __float_as_uint(t13(__fsub_rn(h00, f0))),
                        __float_as_uint(t13(__fsub_rn(h10, f1))),
                        __float_as_uint(t13(__fsub_rn(h01, f2))),
                        __float_as_uint(t13(__fsub_rn(h11, f3))) };

                    const float* base = stH + k8 * 64 + lane * 2;
                    #pragma unroll
                    for (int i = 0; i < 16; ++i) {
                        uint2 bh = *(const uint2*)(base + i * 256);
                        uint2 bl = *(const uint2*)(base + i * 256 + 4096);
                        mmaop(acc[i], ah, bh.x, bh.y);
                        mmaop(acc[i], ah, bl.x, bl.y);
                        mmaop(acc[i], al, bh.x, bh.y);
                        mmaop(acc[i], al, bl.x, bl.y);
                    }
                }
                __syncthreads();
                if (kc < 6) issue(nc, kc + 2, kc & 1);
            }

            // epilogue: bias + relu + dot with W3[:,0], per-thread partials
            #pragma unroll
            for (int i = 0; i < 16; ++i) {
                int c0 = nc * 128 + i * 8 + (lane & 3) * 2;
                int c1 = c0 + 1;
                float v00 = fmaxf(__fadd_rn(acc[i][0], b2s[c0]), 0.0f);
                float v01 = fmaxf(__fadd_rn(acc[i][1], b2s[c1]), 0.0f);
                float v10 = fmaxf(__fadd_rn(acc[i][2], b2s[c0]), 0.0f);
                float v11 = fmaxf(__fadd_rn(acc[i][3], b2s[c1]), 0.0f);
                sp0 = fmaf(v00, w3s[c0], sp0);
                sp0 = fmaf(v01, w3s[c1], sp0);
                sp1 = fmaf(v10, w3s[c0], sp1);
                sp1 = fmaf(v11, w3s[c1], sp1);
            }
        }

        // reduce across the 4 lanes that share each row (fixed shfl order)
        sp0 = __fadd_rn(sp0, __shfl_xor_sync(0xffffffffu, sp0, 1));
        sp0 = __fadd_rn(sp0, __shfl_xor_sync(0xffffffffu, sp0, 2));
        sp1 = __fadd_rn(sp1, __shfl_xor_sync(0xffffffffu, sp1, 1));
        sp1 = __fadd_rn(sp1, __shfl_xor_sync(0xffffffffu, sp1, 2));
        if ((lane & 3) == 0) {
            red[rlo]     = sp0;
            red[rlo + 8] = sp1;
        }
        __syncthreads();

        // sdf + ray update (one thread per ray)
        int pred = 0;
        if (t < 128) {
            float res = __fadd_rn(red[t], b3v);
            float x = px[t], yv = py[t], zv = pz[t];
            float nrm = sqrtf(__fadd_rn(__fadd_rn(__fmul_rn(x, x), __fmul_rn(yv, yv)),
                                        __fmul_rn(zv, zv)));
            float d = __fadd_rn(__fsub_rn(nrm, 0.7f), res);
            dcur = d;
            if (e < 6) {
                int a   = act[t];
                int hit = fabsf(d) < 1e-3f;
                float adv = (a && !hit) ? __fmul_rn(1.41421356237309515f, d) : 0.0f;
                px[t] = __fadd_rn(x,  __fmul_rn(adv, ddx[t]));
                py[t] = __fadd_rn(yv, __fmul_rn(adv, ddy[t]));
                pz[t] = __fadd_rn(zv, __fmul_rn(adv, ddz[t]));
                float tn = __fadd_rn(tt[t], adv);
                tt[t] = tn;
                act[t] = (a && !hit && (tn < 3.5f)) ? 1 : 0;
                pred = (adv != 0.0f);
            }
        }
        int anyAdv = __syncthreads_or(pred);
        // if no ray moved, every remaining eval is bit-identical to dcur
        if (e < 6 && !anyAdv) break;
    }

    if (t < 128) {
        int g = blockIdx.x * 128 + t;
        bool m = fabsf(dcur) < 1e-3f;
        out[3 * g + 0] = m ? px[t] : 0.0f;
        out[3 * g + 1] = m ? py[t] : 0.0f;
        out[3 * g + 2] = m ? pz[t] : 0.0f;
    }
}

extern "C" void kernel_launch(void* const* d_in, const int* in_sizes, int n_in,
                              void* d_out, int out_size) {
    const float* lg = (const float*)d_in[0];
    const float* le = (const float*)d_in[1];
    const float* la = (const float*)d_in[2];
    const float* W1 = (const float*)d_in[3];
    const float* b1 = (const float*)d_in[4];
    const float* W2 = (const float*)d_in[5];
    const float* b2 = (const float*)d_in[6];
    const float* W3 = (const float*)d_in[7];
    const float* b3 = (const float*)d_in[8];
    float* out = (float*)d_out;

    cudaFuncSetAttribute(trace_kernel, cudaFuncAttributeMaxDynamicSharedMemorySize,
                         SMEM_BYTES);
    c1_kernel<<<256, 128>>>(lg, le, la, W1, b1);
    bsplit_kernel<<<256, 256>>>(W2);
    trace_kernel<<<256, 256, SMEM_BYTES>>>(W1, b2, W3, b3, out);
}

// round 11
// speedup vs baseline: 1.4228x; 1.2457x over previous
#include <cuda_runtime.h>
#include <cstdint>

// ---------------------------------------------------------------------------
// PointCloudGenerator: neural-SDF sphere tracing, tensor-core layer-2 GEMM.
// R11: R10 with 3-term 3xTF32 split (ah*bh + ah*bl + al*bh; al*bl term is
// 2^-26 relative — below fp32 accumulate rounding). 25% fewer mma ops.
// A fragments computed in-register from layer-1; B pre-split in fragment
// order, double-buffered cp.async. 256 CTAs, one wave.
// ---------------------------------------------------------------------------

#define OFF_STAGE 0
#define STAGE_F   8192          // floats per stage (hi 4096 + lo 4096)
#define OFF_W1P   16384
#define OFF_B2S   17408
#define OFF_W3S   17664
#define OFF_PX    17920
#define OFF_PY    18048
#define OFF_PZ    18176
#define OFF_TT    18304
#define OFF_DDX   18432
#define OFF_DDY   18560
#define OFF_DDZ   18688
#define OFF_ACT   18816
#define OFF_RED   18944
#define SMEM_FLOATS 19072
#define SMEM_BYTES  (SMEM_FLOATS * 4)

__device__ float g_c1[256];
__device__ float g_Bfh[65536];   // W2^T hi, fragment-order layout
__device__ float g_Bfl[65536];   // W2^T lo, fragment-order layout

__device__ __forceinline__ float t13(float a) {      // truncate to tf32 bits
    return __uint_as_float(__float_as_uint(a) & 0xFFFFE000u);
}
__device__ __forceinline__ void cpa16(float* dst, const float* src) {
    uint32_t s;
    asm("{ .reg .u64 t; cvta.to.shared.u64 t, %1; cvt.u32.u64 %0, t; }"
        : "=r"(s) : "l"(dst));
    asm volatile("cp.async.cg.shared.global [%0], [%1], 16;" :: "r"(s), "l"(src));
}
__device__ __forceinline__ void mmaop(float* c, const uint32_t* a,
                                      uint32_t b0, uint32_t b1) {
    asm("mma.sync.aligned.m16n8k8.row.col.f32.tf32.tf32.f32 "
        "{%0,%1,%2,%3},{%4,%5,%6,%7},{%8,%9},{%0,%1,%2,%3};"
        : "+f"(c[0]), "+f"(c[1]), "+f"(c[2]), "+f"(c[3])
        : "r"(a[0]), "r"(a[1]), "r"(a[2]), "r"(a[3]), "r"(b0), "r"(b1));
}

// c1[j] = b1[j] + sum_k lat[k] * W1[3+k][j]  -- one block per j, double accum
__global__ void c1_kernel(const float* __restrict__ lg, const float* __restrict__ le,
                          const float* __restrict__ la, const float* __restrict__ W1,
                          const float* __restrict__ b1) {
    int j = blockIdx.x;
    int t = threadIdx.x;
    double acc = 0.0;
    for (int k = t; k < 484; k += 128) {
        float lv = (k < 256) ? lg[k] : (k < 356 ? le[k - 256] : la[k - 356]);
        acc += (double)lv * (double)W1[(size_t)(3 + k) * 256 + j];
    }
    #pragma unroll
    for (int o = 16; o > 0; o >>= 1)
        acc += __shfl_down_sync(0xffffffffu, acc, o);
    __shared__ double part[4];
    if ((t & 31) == 0) part[t >> 5] = acc;
    __syncthreads();
    if (t == 0)
        g_c1[j] = (float)(part[0] + part[1] + part[2] + part[3] + (double)b1[j]);
}

// split W2 (k-major [k][n]) into hi/lo, stored in m16n8k8 B-fragment order:
// addr = ((n>>3)*32 + (k>>3))*64 + ((n&7)*4 + (k&3))*2 + ((k>>2)&1)
__global__ void bsplit_kernel(const float* __restrict__ W2) {
    int n = blockIdx.x, k = threadIdx.x;
    float w = W2[k * 256 + n];
    float hi = t13(w);
    float lo = t13(__fsub_rn(w, hi));
    int addr = ((n >> 3) * 32 + (k >> 3)) * 64 + ((n & 7) * 4 + (k & 3)) * 2 +
               ((k >> 2) & 1);
    g_Bfh[addr] = hi;
    g_Bfl[addr] = lo;
}

__global__ void __launch_bounds__(256, 2)
trace_kernel(const float* __restrict__ W1, const float* __restrict__ b2g,
             const float* __restrict__ W3, const float* __restrict__ b3,
             float* __restrict__ out) {
    extern __shared__ float smf[];
    float4* w1p = (float4*)(smf + OFF_W1P);   // [256] {w10,w11,w12,c1}
    float*  b2s = smf + OFF_B2S;
    float*  w3s = smf + OFF_W3S;
    float*  px  = smf + OFF_PX;
    float*  py  = smf + OFF_PY;
    float*  pz  = smf + OFF_PZ;
    float*  tt  = smf + OFF_TT;
    float*  ddx = smf + OFF_DDX;
    float*  ddy = smf + OFF_DDY;
    float*  ddz = smf + OFF_DDZ;
    int*    act = (int*)(smf + OFF_ACT);
    float*  red = smf + OFF_RED;

    const int t    = threadIdx.x;
    const int lane = t & 31;
    const int wid  = t >> 5;
    const int rlo  = wid * 16 + (lane >> 2);   // this thread's low ray row

    // tables
    w1p[t] = make_float4(W1[t], W1[256 + t], W1[512 + t], g_c1[t]);
    b2s[t] = b2g[t];
    w3s[t] = W3[t * 4];     // only column 0 of W3 is live

    // ray setup (mirrors _rays in fp32)
    if (t < 128) {
        int g    = blockIdx.x * 128 + t;
        int view = g >> 14;
        int pix  = g & 16383;
        int iu = pix >> 7, jv = pix & 127;
        float u = (iu + 0.5f) / 128.0f - 0.5f;
        float v = 0.5f - (jv + 0.5f) / 128.0f;
        float nrm = sqrtf(__fadd_rn(__fadd_rn(__fmul_rn(u, u), __fmul_rn(v, v)), 1.0f));
        float d0x = u / nrm, d0y = v / nrm, d0z = -1.0f / nrm;
        float c = 0.86602540378443865f;          // cos(30 deg)
        float s = view ? 0.5f : -0.5f;           // sin(rho), rho = -30, +30
        float dirx = __fadd_rn(__fmul_rn(c, d0x), __fmul_rn(s, d0z));
        float diry = d0y;
        float dirz = __fadd_rn(__fmul_rn(-s, d0x), __fmul_rn(c, d0z));
        ddx[t] = dirx; ddy[t] = diry; ddz[t] = dirz;
        px[t] = __fadd_rn(__fmul_rn(s, 2.2f), __fmul_rn(2.2f, dirx));
        py[t] = __fmul_rn(2.2f, diry);
        pz[t] = __fadd_rn(__fmul_rn(c, 2.2f), __fmul_rn(2.2f, dirz));
        tt[t] = 0.0f;
        act[t] = 1;
    }
    __syncthreads();

    const float b3v = b3[0];
    float dcur = 0.0f;

    // stream B chunk (nc, kc) into stage s: 64 frag-blocks x 64 floats, hi+lo
    auto issue = [&](int nc, int kc, int s) {
        float* stH = smf + OFF_STAGE + s * STAGE_F;
        float* stL = stH + 4096;
        #pragma unroll
        for (int i = 0; i < 4; ++i) {
            int tr = t + i * 256;               // 0..1023
            int bl = tr >> 4, q = tr & 15;
            int gb = nc * 512 + kc * 4 + (bl >> 2) * 32 + (bl & 3);
            cpa16(stH + bl * 64 + q * 4, g_Bfh + gb * 64 + q * 4);
            cpa16(stL + bl * 64 + q * 4, g_Bfl + gb * 64 + q * 4);
        }
        asm volatile("cp.async.commit_group;" ::: "memory");
    };

    for (int e = 0; e < 7; ++e) {
        // this thread's two rays, in registers
        float xlo = px[rlo],     ylo = py[rlo],     zlo = pz[rlo];
        float xhi = px[rlo + 8], yhi = py[rlo + 8], zhi = pz[rlo + 8];
        float sp0 = 0.0f, sp1 = 0.0f;

        #pragma unroll 1
        for (int nc = 0; nc < 2; ++nc) {
            float acc[16][4];
            #pragma unroll
            for (int i = 0; i < 16; ++i)
                #pragma unroll
                for (int j = 0; j < 4; ++j) acc[i][j] = 0.0f;

            issue(nc, 0, 0);
            issue(nc, 1, 1);

            #pragma unroll 1
            for (int kc = 0; kc < 8; ++kc) {
                if (kc < 7) asm volatile("cp.async.wait_group 1;" ::: "memory");
                else        asm volatile("cp.async.wait_group 0;" ::: "memory");
                __syncthreads();

                const float* stH = smf + OFF_STAGE + (kc & 1) * STAGE_F;
                #pragma unroll
                for (int k8 = 0; k8 < 4; ++k8) {
                    // A fragment: layer-1 for (2 rays) x (2 k), in-register
                    int k0 = kc * 32 + k8 * 8 + (lane & 3);
                    float4 w0 = w1p[k0];
                    float4 w1 = w1p[k0 + 4];
                    float h00 = fmaxf(fmaf(xlo, w0.x, fmaf(ylo, w0.y,
                                      fmaf(zlo, w0.z, w0.w))), 0.0f);
                    float h10 = fmaxf(fmaf(xhi, w0.x, fmaf(yhi, w0.y,
                                      fmaf(zhi, w0.z, w0.w))), 0.0f);
                    float h01 = fmaxf(fmaf(xlo, w1.x, fmaf(ylo, w1.y,
                                      fmaf(zlo, w1.z, w1.w))), 0.0f);
                    float h11 = fmaxf(fmaf(xhi, w1.x, fmaf(yhi, w1.y,
                                      fmaf(zhi, w1.z, w1.w))), 0.0f);
                    float f0 = t13(h00), f1 = t13(h10), f2 = t13(h01), f3 = t13(h11);
                    uint32_t ah[4] = { __float_as_uint(f0), __float_as_uint(f1),
                                       __float_as_uint(f2), __float_as_uint(f3) };
                    uint32_t al[4] = {
                        __float_as_uint(t13(__fsub_rn(h00, f0))),
                        __float_as_uint(t13(__fsub_rn(h10, f1))),
                        __float_as_uint(t13(__fsub_rn(h01, f2))),
                        __float_as_uint(t13(__fsub_rn(h11, f3))) };

                    const float* base = stH + k8 * 64 + lane * 2;
                    #pragma unroll
                    for (int i = 0; i < 16; ++i) {
                        uint2 bh = *(const uint2*)(base + i * 256);
                        uint2 bl = *(const uint2*)(base + i * 256 + 4096);
                        mmaop(acc[i], ah, bh.x, bh.y);   // ah*bh
                        mmaop(acc[i], ah, bl.x, bl.y);   // ah*bl
                        mmaop(acc[i], al, bh.x, bh.y);   // al*bh (al*bl ~2^-26: dropped)
                    }
                }
                __syncthreads();
                if (kc < 6) issue(nc, kc + 2, kc & 1);
            }

            // epilogue: bias + relu + dot with W3[:,0], per-thread partials
            #pragma unroll
            for (int i = 0; i < 16; ++i) {
                int c0 = nc * 128 + i * 8 + (lane & 3) * 2;
                int c1 = c0 + 1;
                float v00 = fmaxf(__fadd_rn(acc[i][0], b2s[c0]), 0.0f);
                float v01 = fmaxf(__fadd_rn(acc[i][1], b2s[c1]), 0.0f);
                float v10 = fmaxf(__fadd_rn(acc[i][2], b2s[c0]), 0.0f);
                float v11 = fmaxf(__fadd_rn(acc[i][3], b2s[c1]), 0.0f);
                sp0 = fmaf(v00, w3s[c0], sp0);
                sp0 = fmaf(v01, w3s[c1], sp0);
                sp1 = fmaf(v10, w3s[c0], sp1);
                sp1 = fmaf(v11, w3s[c1], sp1);
            }
        }

        // reduce across the 4 lanes that share each row (fixed shfl order)
        sp0 = __fadd_rn(sp0, __shfl_xor_sync(0xffffffffu, sp0, 1));
        sp0 = __fadd_rn(sp0, __shfl_xor_sync(0xffffffffu, sp0, 2));
        sp1 = __fadd_rn(sp1, __shfl_xor_sync(0xffffffffu, sp1, 1));
        sp1 = __fadd_rn(sp1, __shfl_xor_sync(0xffffffffu, sp1, 2));
        if ((lane & 3) == 0) {
            red[rlo]     = sp0;
            red[rlo + 8] = sp1;
        }
        __syncthreads();

        // sdf + ray update (one thread per ray)
        int pred = 0;
        if (t < 128) {
            float res = __fadd_rn(red[t], b3v);
            float x = px[t], yv = py[t], zv = pz[t];
            float nrm = sqrtf(__fadd_rn(__fadd_rn(__fmul_rn(x, x), __fmul_rn(yv, yv)),
                                        __fmul_rn(zv, zv)));
            float d = __fadd_rn(__fsub_rn(nrm, 0.7f), res);
            dcur = d;
            if (e < 6) {
                int a   = act[t];
                int hit = fabsf(d) < 1e-3f;
                float adv = (a && !hit) ? __fmul_rn(1.41421356237309515f, d) : 0.0f;
                px[t] = __fadd_rn(x,  __fmul_rn(adv, ddx[t]));
                py[t] = __fadd_rn(yv, __fmul_rn(adv, ddy[t]));
                pz[t] = __fadd_rn(zv, __fmul_rn(adv, ddz[t]));
                float tn = __fadd_rn(tt[t], adv);
                tt[t] = tn;
                act[t] = (a && !hit && (tn < 3.5f)) ? 1 : 0;
                pred = (adv != 0.0f);
            }
        }
        int anyAdv = __syncthreads_or(pred);
        // if no ray moved, every remaining eval is bit-identical to dcur
        if (e < 6 && !anyAdv) break;
    }

    if (t < 128) {
        int g = blockIdx.x * 128 + t;
        bool m = fabsf(dcur) < 1e-3f;
        out[3 * g + 0] = m ? px[t] : 0.0f;
        out[3 * g + 1] = m ? py[t] : 0.0f;
        out[3 * g + 2] = m ? pz[t] : 0.0f;
    }
}

extern "C" void kernel_launch(void* const* d_in, const int* in_sizes, int n_in,
                              void* d_out, int out_size) {
    const float* lg = (const float*)d_in[0];
    const float* le = (const float*)d_in[1];
    const float* la = (const float*)d_in[2];
    const float* W1 = (const float*)d_in[3];
    const float* b1 = (const float*)d_in[4];
    const float* W2 = (const float*)d_in[5];
    const float* b2 = (const float*)d_in[6];
    const float* W3 = (const float*)d_in[7];
    const float* b3 = (const float*)d_in[8];
    float* out = (float*)d_out;

    cudaFuncSetAttribute(trace_kernel, cudaFuncAttributeMaxDynamicSharedMemorySize,
                         SMEM_BYTES);
    c1_kernel<<<256, 128>>>(lg, le, la, W1, b1);
    bsplit_kernel<<<256, 256>>>(W2);
    trace_kernel<<<256, 256, SMEM_BYTES>>>(W1, b2, W3, b3, out);
}